// round 5
// baseline (speedup 1.0000x reference)
#include <cuda_runtime.h>
#include <cuda_bf16.h>

#define NBINS 10
#define NCLS  128
#define NLAB  (NCLS * 3)   // 384
#define ALPHA 0.999f

// ---------------- device scratch (self-resetting: last block zeroes after use) ----
__device__ float g_loss = 0.f;
__device__ float g_msum = 0.f;
__device__ float g_gd[NBINS] = {};
__device__ float g_lab[NLAB] = {};
__device__ unsigned int g_ticket = 0;

__device__ __forceinline__ float rcp_approx(float x) {
    float r;
    asm("rcp.approx.f32 %0, %1;" : "=f"(r) : "f"(x));
    return r;
}

// ---------------- single fused kernel: warp per row of 128 classes ----------------
// lane l handles classes 4l..4l+3 (one float4 of logits + one of targets).
// GD hist: fire-and-forget smem atomics (lane-private, conflict-free).
// Label hist: register cumulative counters (no memory ops at all).
__global__ __launch_bounds__(256, 4)
void ghm_fused_kernel(const float4* __restrict__ logits,
                      const float4* __restrict__ tprob,
                      const float*  __restrict__ mask,
                      const float*  __restrict__ gd_ema,
                      const float*  __restrict__ lab_ema,
                      float* __restrict__ out,
                      int rows)
{
    // weight tables: bank == lane everywhere (conflict-free)
    __shared__ float s_gdr[NBINS * 32];   // [bi*32 + lane] = rsqrt(gd_ema[bi])
    __shared__ float s_labw[12 * 32];     // [j*32 + lane]  = rsqrt(lab_ema[12*lane + j])
    // lane-private GD histogram: [warp][bin][lane] -> bank == lane
    __shared__ float s_gdp[8 * NBINS * 32];   // 2560 floats
    __shared__ float s_labh[8 * 12 * 32];     // label staging (written once at end)
    __shared__ float s_loss[8], s_m[8];
    __shared__ float s_red[NBINS * 32];
    __shared__ int   s_last;

    const int tid  = threadIdx.x;
    const int lane = tid & 31;
    const int warp = tid >> 5;

    for (int i = tid; i < NBINS * 32; i += 256) s_gdr[i] = rsqrtf(__ldg(&gd_ema[i >> 5]));
    for (int i = tid; i < 12 * 32; i += 256)
        s_labw[i] = rsqrtf(__ldg(&lab_ema[12 * (i & 31) + (i >> 5)]));
    for (int i = tid; i < 8 * NBINS * 32; i += 256) s_gdp[i] = 0.f;
    __syncthreads();

    const int gwarp  = blockIdx.x * 8 + warp;
    const int nwarps = gridDim.x * 8;

    float loss_acc = 0.f;
    float m_acc    = 0.f;
    float c1[4], c2[4];                 // cumulative label counters per e-slot
#pragma unroll
    for (int e = 0; e < 4; e++) { c1[e] = 0.f; c2[e] = 0.f; }

    const int gd_base = warp * (NBINS * 32) + lane;  // + bi*32

    const float4* lp = logits + (size_t)gwarp * 32 + lane;
    const float4* tp = tprob  + (size_t)gwarp * 32 + lane;
    const float*  mp = mask + gwarp;
    const size_t  step = (size_t)nwarps * 32;

    // ---- software-pipelined main loop ----
    int row = gwarp;
    float4 x4 = make_float4(0.f,0.f,0.f,0.f);
    float4 t4 = make_float4(0.f,0.f,0.f,0.f);
    float  m  = 0.f;
    if (row < rows) { x4 = *lp; t4 = *tp; m = *mp; }

    while (row < rows) {
        const int nrow = row + nwarps;
        float4 x4n, t4n; float mn;
        if (nrow < rows) {
            lp += step; tp += step; mp += nwarps;
            x4n = *lp; t4n = *tp; mn = *mp;   // issued long before use
        } else {
            x4n = x4; t4n = t4; mn = 0.f;
        }

        m_acc += m;
        float xs[4] = {x4.x, x4.y, x4.z, x4.w};
        float ts[4] = {t4.x, t4.y, t4.z, t4.w};

#pragma unroll
        for (int e = 0; e < 4; e++) {
            float x = xs[e];
            float t = __saturatef(ts[e]);

            float ax  = fabsf(x);
            float ee  = __expf(-ax);                 // exp(-|x|) in (0,1]
            float d   = 1.f + ee;
            float r   = rcp_approx(d);               // 1/(1+e) in [0.5,1]
            float sig = (x >= 0.f) ? r : 1.f - r;    // sigmoid(x)
            float raw = fmaxf(x, 0.f) - x * t + __logf(d);
            float g   = fabsf(sig - t);

            int bi = min(__float2int_rz(g * 10.f), NBINS - 1);

            // label 3-way bin via two predicates (shared by hist + weight index)
            bool b1 = (t >= (1.f / 3.f));
            bool b2 = (t >= (2.f / 3.f));
            if (b1) c1[e] += m;
            if (b2) c2[e] += m;
            int j = e * 96 + lane + (b1 ? 32 : 0) + (b2 ? 32 : 0);

            float w = s_gdr[bi * 32 + lane] * s_labw[j];
            loss_acc = fmaf(raw * w, m, loss_acc);

            // GD histogram: fire-and-forget, conflict-free shared atomic
            atomicAdd(&s_gdp[gd_base + bi * 32], m);
        }

        x4 = x4n; t4 = t4n; m = mn;
        row = nrow;
    }

    // ---- stage label counts from registers (counts: k0 = m_acc - c1, k1 = c1 - c2, k2 = c2)
    const int lab_stage = warp * (12 * 32) + lane;
#pragma unroll
    for (int e = 0; e < 4; e++) {
        s_labh[lab_stage + (3 * e + 0) * 32] = m_acc - c1[e];
        s_labh[lab_stage + (3 * e + 1) * 32] = c1[e] - c2[e];
        s_labh[lab_stage + (3 * e + 2) * 32] = c2[e];
    }

    // ---- loss / mask warp reductions ----
#pragma unroll
    for (int off = 16; off > 0; off >>= 1) {
        loss_acc += __shfl_down_sync(0xffffffffu, loss_acc, off);
        m_acc    += __shfl_down_sync(0xffffffffu, m_acc, off);
    }
    if (lane == 0) { s_loss[warp] = loss_acc; s_m[warp] = m_acc; }
    __syncthreads();

    // ---- block-level histogram reduction -> global atomics ----
    if (tid < NBINS * 32) {
        float v = 0.f;
#pragma unroll
        for (int w = 0; w < 8; w++) v += s_gdp[w * (NBINS * 32) + tid];
        s_red[tid] = v;
    }
    for (int t = tid; t < NLAB; t += 256) {
        int l = t / 12, j = t % 12;
        float v = 0.f;
#pragma unroll
        for (int w = 0; w < 8; w++) v += s_labh[w * (12 * 32) + j * 32 + l];
        atomicAdd(&g_lab[t], v);
    }
    __syncthreads();
    if (warp < NBINS) {
        float v = s_red[warp * 32 + lane];
#pragma unroll
        for (int off = 16; off > 0; off >>= 1)
            v += __shfl_down_sync(0xffffffffu, v, off);
        if (lane == 0) atomicAdd(&g_gd[warp], v);
    }
    if (tid == 0) {
        float L = 0.f, M = 0.f;
#pragma unroll
        for (int w = 0; w < 8; w++) { L += s_loss[w]; M += s_m[w]; }
        atomicAdd(&g_loss, L);
        atomicAdd(&g_msum, M * 4.0f);   // each lane's m covered 4 elements
    }

    // ---- last-block finalize ----
    __threadfence();
    __syncthreads();
    if (tid == 0) {
        unsigned int tk = atomicAdd(&g_ticket, 1u);
        s_last = (tk == gridDim.x - 1) ? 1 : 0;
    }
    __syncthreads();
    if (!s_last) return;
    __threadfence();   // acquire side

    // label histogram EMA (384 bins over 256 threads: tid and tid+256)
    float h0 = (tid < NLAB) ? g_lab[tid] : 0.f;
    float h1 = (tid < NLAB - 256) ? g_lab[tid + 256] : 0.f;
    s_red[tid] = h0 + h1;
    __syncthreads();
#pragma unroll
    for (int s = 128; s > 0; s >>= 1) {
        if (tid < s) s_red[tid] += s_red[tid + s];
        __syncthreads();
    }
    float hsum = s_red[0];
    __syncthreads();

    float inv = (float)NLAB / fmaxf(hsum, 1e-10f);
    float ema0 = 0.f, ema1 = 0.f;
    if (tid < NLAB)       ema0 = __ldg(&lab_ema[tid])       * ALPHA + (1.f - ALPHA) * (h0 * inv);
    if (tid < NLAB - 256) ema1 = __ldg(&lab_ema[tid + 256]) * ALPHA + (1.f - ALPHA) * (h1 * inv);
    s_red[tid] = ema0 + ema1;
    __syncthreads();
#pragma unroll
    for (int s = 128; s > 0; s >>= 1) {
        if (tid < s) s_red[tid] += s_red[tid + s];
        __syncthreads();
    }
    float esum = s_red[0];
    float sc = (float)NLAB / fmaxf(esum, 1e-10f);
    if (tid < NLAB)       out[1 + NBINS + tid]       = ema0 * sc;
    if (tid < NLAB - 256) out[1 + NBINS + tid + 256] = ema1 * sc;

    // GD EMA + loss (tiny, one thread)
    if (tid == 0) {
        float gd[NBINS];
        float hs = 0.f;
#pragma unroll
        for (int b = 0; b < NBINS; b++) { gd[b] = g_gd[b]; hs += gd[b]; }
        hs = fmaxf(hs, 1e-10f);
        float e[NBINS]; float es = 0.f;
#pragma unroll
        for (int b = 0; b < NBINS; b++) {
            e[b] = __ldg(&gd_ema[b]) * ALPHA + (1.f - ALPHA) * (gd[b] / hs * (float)NBINS);
            es += e[b];
        }
        es = fmaxf(es, 1e-10f);
#pragma unroll
        for (int b = 0; b < NBINS; b++) out[1 + b] = e[b] / es * (float)NBINS;

        out[0] = g_loss / fmaxf(g_msum, 1e-10f);
    }

    // ---- reset scratch for the next launch ----
    if (tid < NLAB)       g_lab[tid] = 0.f;
    if (tid < NLAB - 256) g_lab[tid + 256] = 0.f;
    if (tid == 0) {
        g_loss = 0.f; g_msum = 0.f;
#pragma unroll
        for (int b = 0; b < NBINS; b++) g_gd[b] = 0.f;
        __threadfence();
        g_ticket = 0u;
    }
}

extern "C" void kernel_launch(void* const* d_in, const int* in_sizes, int n_in,
                              void* d_out, int out_size)
{
    const float* logits  = (const float*)d_in[0];
    const float* tprob   = (const float*)d_in[1];
    const float* mask    = (const float*)d_in[2];
    const float* gd_ema  = (const float*)d_in[3];
    const float* lab_ema = (const float*)d_in[4];

    const int total = in_sizes[0];
    const int rows  = total / NCLS;      // 65536

    ghm_fused_kernel<<<148 * 5, 256>>>((const float4*)logits, (const float4*)tprob,
                                       mask, gd_ema, lab_ema, (float*)d_out, rows);
}

// round 6
// speedup vs baseline: 1.1189x; 1.1189x over previous
#include <cuda_runtime.h>
#include <cuda_bf16.h>

#define NBINS 10
#define NCLS  128
#define NLAB  (NCLS * 3)   // 384
#define ALPHA 0.999f

// ---------------- device scratch (self-resetting: last block zeroes after use) ----
__device__ float g_loss = 0.f;
__device__ float g_msum = 0.f;
__device__ float g_gd[NBINS] = {};
__device__ float g_lab[NLAB] = {};
__device__ unsigned int g_ticket = 0;

__device__ __forceinline__ float rcp_approx(float x) {
    float r;
    asm("rcp.approx.f32 %0, %1;" : "=f"(r) : "f"(x));
    return r;
}

// ---------------- single fused kernel: warp per row of 128 classes ----------------
// lane l handles classes 4l..4l+3 (one float4 of logits + one of targets).
// Histograms are plain smem RMW, but split into DISTINCT shared arrays so ptxas
// can prove non-aliasing across the 4 unrolled e-slots (breaks the serial
// LDS->FADD->STS dependency chain):
//   - label: one array per e-slot (provably disjoint bins) -> 4 independent chains
//   - GD:    two parity arrays (e<2 / e>=2)               -> 2 independent chains
__global__ __launch_bounds__(256, 5)
void ghm_fused_kernel(const float4* __restrict__ logits,
                      const float4* __restrict__ tprob,
                      const float*  __restrict__ mask,
                      const float*  __restrict__ gd_ema,
                      const float*  __restrict__ lab_ema,
                      float* __restrict__ out,
                      int rows)
{
    // weight tables: bank == lane everywhere (conflict-free)
    __shared__ float s_gdr[NBINS * 32];   // [bi*32 + lane] = rsqrt(gd_ema[bi])
    __shared__ float s_labw[12 * 32];     // [j*32 + lane]  = rsqrt(lab_ema[12*lane + j])
    // GD parity histograms: [warp][bin][lane]
    __shared__ float s_gdA[8 * NBINS * 32];   // e = 0,1
    __shared__ float s_gdB[8 * NBINS * 32];   // e = 2,3
    // label histograms, one array per e-slot: [warp][tb][lane]
    __shared__ float s_lab0[8 * 3 * 32];
    __shared__ float s_lab1[8 * 3 * 32];
    __shared__ float s_lab2[8 * 3 * 32];
    __shared__ float s_lab3[8 * 3 * 32];
    __shared__ float s_loss[8], s_m[8];
    __shared__ float s_red[NBINS * 32];
    __shared__ int   s_last;

    const int tid  = threadIdx.x;
    const int lane = tid & 31;
    const int warp = tid >> 5;

    for (int i = tid; i < NBINS * 32; i += 256) s_gdr[i] = rsqrtf(__ldg(&gd_ema[i >> 5]));
    for (int i = tid; i < 12 * 32; i += 256)
        s_labw[i] = rsqrtf(__ldg(&lab_ema[12 * (i & 31) + (i >> 5)]));
    for (int i = tid; i < 8 * NBINS * 32; i += 256) { s_gdA[i] = 0.f; s_gdB[i] = 0.f; }
    for (int i = tid; i < 8 * 3 * 32; i += 256) {
        s_lab0[i] = 0.f; s_lab1[i] = 0.f; s_lab2[i] = 0.f; s_lab3[i] = 0.f;
    }
    __syncthreads();

    const int gwarp  = blockIdx.x * 8 + warp;
    const int nwarps = gridDim.x * 8;

    float loss_acc = 0.f;
    float m_acc    = 0.f;

    const int gd_base  = warp * (NBINS * 32) + lane;  // + bi*32
    const int lab_base = warp * (3 * 32) + lane;      // + tb*32

    const float4* lp = logits + (size_t)gwarp * 32 + lane;
    const float4* tp = tprob  + (size_t)gwarp * 32 + lane;
    const float*  mp = mask + gwarp;
    const size_t  step = (size_t)nwarps * 32;

    // ---- software-pipelined main loop ----
    int row = gwarp;
    float4 x4 = make_float4(0.f,0.f,0.f,0.f);
    float4 t4 = make_float4(0.f,0.f,0.f,0.f);
    float  m  = 0.f;
    if (row < rows) { x4 = *lp; t4 = *tp; m = *mp; }

    while (row < rows) {
        const int nrow = row + nwarps;
        float4 x4n, t4n; float mn;
        if (nrow < rows) {
            lp += step; tp += step; mp += nwarps;
            x4n = *lp; t4n = *tp; mn = *mp;   // issued long before use
        } else {
            x4n = x4; t4n = t4; mn = 0.f;
        }

        m_acc += m;
        float xs[4] = {x4.x, x4.y, x4.z, x4.w};
        float ts[4] = {t4.x, t4.y, t4.z, t4.w};

#pragma unroll
        for (int e = 0; e < 4; e++) {
            float x = xs[e];
            float t = __saturatef(ts[e]);

            float ax  = fabsf(x);
            float ee  = __expf(-ax);                 // exp(-|x|) in (0,1]
            float d   = 1.f + ee;
            float r   = rcp_approx(d);               // 1/(1+e) in [0.5,1]
            float sig = (x >= 0.f) ? r : 1.f - r;    // sigmoid(x)
            float raw = fmaxf(x, 0.f) - x * t + __logf(d);
            float g   = fabsf(sig - t);

            int bi = min(__float2int_rz(g * 10.f), NBINS - 1);
            int tb = min(__float2int_rz(t * 3.f), 2);

            float w = s_gdr[bi * 32 + lane] * s_labw[(3 * e + tb) * 32 + lane];
            loss_acc = fmaf(raw * w, m, loss_acc);

            // GD RMW: two independent parity chains (distinct arrays)
            if (e < 2) s_gdA[gd_base + bi * 32] += m;
            else       s_gdB[gd_base + bi * 32] += m;
            // label RMW: fully independent per e-slot (distinct arrays)
            if      (e == 0) s_lab0[lab_base + tb * 32] += m;
            else if (e == 1) s_lab1[lab_base + tb * 32] += m;
            else if (e == 2) s_lab2[lab_base + tb * 32] += m;
            else             s_lab3[lab_base + tb * 32] += m;
        }

        x4 = x4n; t4 = t4n; m = mn;
        row = nrow;
    }

    // ---- loss / mask warp reductions ----
#pragma unroll
    for (int off = 16; off > 0; off >>= 1) {
        loss_acc += __shfl_down_sync(0xffffffffu, loss_acc, off);
        m_acc    += __shfl_down_sync(0xffffffffu, m_acc, off);
    }
    if (lane == 0) { s_loss[warp] = loss_acc; s_m[warp] = m_acc; }
    __syncthreads();

    // ---- block-level histogram reduction -> global atomics ----
    if (tid < NBINS * 32) {
        float v = 0.f;
#pragma unroll
        for (int w = 0; w < 8; w++)
            v += s_gdA[w * (NBINS * 32) + tid] + s_gdB[w * (NBINS * 32) + tid];
        s_red[tid] = v;
    }
    // label: global bin t = 12*l + j,  j = 3e + tb
    for (int t = tid; t < NLAB; t += 256) {
        int l = t / 12, j = t % 12;
        int e = j / 3, tb = j % 3;
        const float* arr = (e == 0) ? s_lab0 : (e == 1) ? s_lab1 : (e == 2) ? s_lab2 : s_lab3;
        float v = 0.f;
#pragma unroll
        for (int w = 0; w < 8; w++) v += arr[w * (3 * 32) + tb * 32 + l];
        atomicAdd(&g_lab[t], v);
    }
    __syncthreads();
    if (warp < NBINS) {
        float v = s_red[warp * 32 + lane];
#pragma unroll
        for (int off = 16; off > 0; off >>= 1)
            v += __shfl_down_sync(0xffffffffu, v, off);
        if (lane == 0) atomicAdd(&g_gd[warp], v);
    }
    if (tid == 0) {
        float L = 0.f, M = 0.f;
#pragma unroll
        for (int w = 0; w < 8; w++) { L += s_loss[w]; M += s_m[w]; }
        atomicAdd(&g_loss, L);
        atomicAdd(&g_msum, M * 4.0f);   // each lane's m covered 4 elements
    }

    // ---- last-block finalize ----
    __threadfence();
    __syncthreads();
    if (tid == 0) {
        unsigned int tk = atomicAdd(&g_ticket, 1u);
        s_last = (tk == gridDim.x - 1) ? 1 : 0;
    }
    __syncthreads();
    if (!s_last) return;
    __threadfence();   // acquire side

    // label histogram EMA (384 bins over 256 threads: tid and tid+256)
    float h0 = (tid < NLAB) ? g_lab[tid] : 0.f;
    float h1 = (tid < NLAB - 256) ? g_lab[tid + 256] : 0.f;
    s_red[tid] = h0 + h1;
    __syncthreads();
#pragma unroll
    for (int s = 128; s > 0; s >>= 1) {
        if (tid < s) s_red[tid] += s_red[tid + s];
        __syncthreads();
    }
    float hsum = s_red[0];
    __syncthreads();

    float inv = (float)NLAB / fmaxf(hsum, 1e-10f);
    float ema0 = 0.f, ema1 = 0.f;
    if (tid < NLAB)       ema0 = __ldg(&lab_ema[tid])       * ALPHA + (1.f - ALPHA) * (h0 * inv);
    if (tid < NLAB - 256) ema1 = __ldg(&lab_ema[tid + 256]) * ALPHA + (1.f - ALPHA) * (h1 * inv);
    s_red[tid] = ema0 + ema1;
    __syncthreads();
#pragma unroll
    for (int s = 128; s > 0; s >>= 1) {
        if (tid < s) s_red[tid] += s_red[tid + s];
        __syncthreads();
    }
    float esum = s_red[0];
    float sc = (float)NLAB / fmaxf(esum, 1e-10f);
    if (tid < NLAB)       out[1 + NBINS + tid]       = ema0 * sc;
    if (tid < NLAB - 256) out[1 + NBINS + tid + 256] = ema1 * sc;

    // GD EMA + loss (tiny, one thread)
    if (tid == 0) {
        float gd[NBINS];
        float hs = 0.f;
#pragma unroll
        for (int b = 0; b < NBINS; b++) { gd[b] = g_gd[b]; hs += gd[b]; }
        hs = fmaxf(hs, 1e-10f);
        float e[NBINS]; float es = 0.f;
#pragma unroll
        for (int b = 0; b < NBINS; b++) {
            e[b] = __ldg(&gd_ema[b]) * ALPHA + (1.f - ALPHA) * (gd[b] / hs * (float)NBINS);
            es += e[b];
        }
        es = fmaxf(es, 1e-10f);
#pragma unroll
        for (int b = 0; b < NBINS; b++) out[1 + b] = e[b] / es * (float)NBINS;

        out[0] = g_loss / fmaxf(g_msum, 1e-10f);
    }

    // ---- reset scratch for the next launch ----
    if (tid < NLAB)       g_lab[tid] = 0.f;
    if (tid < NLAB - 256) g_lab[tid + 256] = 0.f;
    if (tid == 0) {
        g_loss = 0.f; g_msum = 0.f;
#pragma unroll
        for (int b = 0; b < NBINS; b++) g_gd[b] = 0.f;
        __threadfence();
        g_ticket = 0u;
    }
}

extern "C" void kernel_launch(void* const* d_in, const int* in_sizes, int n_in,
                              void* d_out, int out_size)
{
    const float* logits  = (const float*)d_in[0];
    const float* tprob   = (const float*)d_in[1];
    const float* mask    = (const float*)d_in[2];
    const float* gd_ema  = (const float*)d_in[3];
    const float* lab_ema = (const float*)d_in[4];

    const int total = in_sizes[0];
    const int rows  = total / NCLS;      // 65536

    ghm_fused_kernel<<<148 * 5, 256>>>((const float4*)logits, (const float4*)tprob,
                                       mask, gd_ema, lab_ema, (float*)d_out, rows);
}